// round 3
// baseline (speedup 1.0000x reference)
#include <cuda_runtime.h>

#define S   3
#define Bn  4096
#define DIN 1024
#define H1d 512
#define H2d 384
#define H3d 256
#define Dd  128
#define Kc  512
#define Cc  3
#define INV_T 10.0f

// ---------------- scratch (device globals; no allocation allowed) ----------------
__device__ float g_h1[S*Bn*H1d];
__device__ float g_h2[S*Bn*H2d];
__device__ float g_h3[S*Bn*H3d];
__device__ float g_emb[S*Bn*Dd];
__device__ float g_tanhbuf[S*Bn*Dd];
__device__ float g_score[S*Bn];
__device__ float g_res[Bn*Dd];
__device__ float g_qsum[Bn*Dd];
__device__ float g_dots[Bn*Kc];
__device__ float g_Et[Cc*Dd*Kc];
__device__ float g_enorm2[Cc*Kc];
__device__ float g_einvn[Cc*Kc];
__device__ float g_z1[Bn*Dd];
__device__ float g_z1t[Dd*Bn];
__device__ float g_z2[S*Bn*Dd];
__device__ float g_z2t[S*Dd*Bn];
__device__ float g_reflsum[Bn];
__device__ float g_btwsum[S*Bn];
__device__ float g_diag[Bn];
__device__ float g_pos[S*Bn];
__device__ float g_cbsum[Cc*Dd];

// ---------------- helpers ----------------
__device__ __forceinline__ float blockReduceSum128(float v) {
    __shared__ float sr[128];
    sr[threadIdx.x] = v;
    __syncthreads();
    #pragma unroll
    for (int s = 64; s > 0; s >>= 1) {
        if (threadIdx.x < s) sr[threadIdx.x] += sr[threadIdx.x + s];
        __syncthreads();
    }
    float r = sr[0];
    __syncthreads();
    return r;
}

// ---------------- generic 128x128 tiled SGEMM, 8x8 per thread ----------------
// EPI: 0 = none, 1 = bias+relu, 2 = bias, 3 = tanh(x+bias)
template<int EPI>
__global__ void __launch_bounds__(256)
sgemm_k(const float* __restrict__ A, const float* __restrict__ Bm,
        const float* __restrict__ bias, float* __restrict__ C,
        int N, int K, int sA, int sB, int sBias, int sC)
{
    int bz = blockIdx.z;
    A  += (size_t)bz * sA;
    Bm += (size_t)bz * sB;
    C  += (size_t)bz * sC;
    if (EPI != 0) bias += (size_t)bz * sBias;

    __shared__ float As[8][132];
    __shared__ float Bs[8][128];

    int tid = threadIdx.x;
    int tx = tid & 15, ty = tid >> 4;
    int row0 = blockIdx.y * 128, col0 = blockIdx.x * 128;

    float acc[8][8];
    #pragma unroll
    for (int i = 0; i < 8; i++)
        #pragma unroll
        for (int j = 0; j < 8; j++) acc[i][j] = 0.f;

    int am = tid >> 1, ak = (tid & 1) * 4;
    int bk = tid >> 5, bn = (tid & 31) * 4;

    for (int k0 = 0; k0 < K; k0 += 8) {
        float4 av = *(const float4*)(A + (size_t)(row0 + am) * K + k0 + ak);
        float4 bv = *(const float4*)(Bm + (size_t)(k0 + bk) * N + col0 + bn);
        As[ak + 0][am] = av.x;
        As[ak + 1][am] = av.y;
        As[ak + 2][am] = av.z;
        As[ak + 3][am] = av.w;
        *(float4*)(&Bs[bk][bn]) = bv;
        __syncthreads();
        #pragma unroll
        for (int kk = 0; kk < 8; kk++) {
            float a[8], b[8];
            #pragma unroll
            for (int i = 0; i < 8; i++) a[i] = As[kk][ty * 8 + i];
            #pragma unroll
            for (int j = 0; j < 8; j++) b[j] = Bs[kk][tx * 8 + j];
            #pragma unroll
            for (int i = 0; i < 8; i++)
                #pragma unroll
                for (int j = 0; j < 8; j++) acc[i][j] = fmaf(a[i], b[j], acc[i][j]);
        }
        __syncthreads();
    }

    #pragma unroll
    for (int i = 0; i < 8; i++) {
        int row = row0 + ty * 8 + i;
        float* crow = C + (size_t)row * N + col0 + tx * 8;
        #pragma unroll
        for (int j = 0; j < 8; j++) {
            float v = acc[i][j];
            if (EPI != 0) {
                float bb = bias[col0 + tx * 8 + j];
                if (EPI == 1)      v = fmaxf(v + bb, 0.f);
                else if (EPI == 2) v = v + bb;
                else               v = tanhf(v + bb);
            }
            crow[j] = v;
        }
    }
}

// ---------------- fused exp-rowsum "GEMM" for contrastive terms ----------------
// which==0: Z1 @ Z1^T -> g_reflsum ; which==1..3: Z1 @ Z2[s]^T -> g_btwsum[s]
__global__ void __launch_bounds__(256)
rowsum_exp_k(int which)
{
    const float* __restrict__ Z  = g_z1;                       // [4096,128]
    const float* __restrict__ Zt = (which == 0) ? g_z1t
                                 : g_z2t + (size_t)(which - 1) * Dd * Bn;  // [128,4096]
    float* __restrict__ rowsum   = (which == 0) ? g_reflsum
                                 : g_btwsum + (size_t)(which - 1) * Bn;

    __shared__ float As[8][132];
    __shared__ float Bs[8][128];
    __shared__ float red[128][17];

    int tid = threadIdx.x;
    int tx = tid & 15, ty = tid >> 4;
    int row0 = blockIdx.y * 128, col0 = blockIdx.x * 128;

    float acc[8][8];
    #pragma unroll
    for (int i = 0; i < 8; i++)
        #pragma unroll
        for (int j = 0; j < 8; j++) acc[i][j] = 0.f;

    int am = tid >> 1, ak = (tid & 1) * 4;
    int bk = tid >> 5, bn = (tid & 31) * 4;

    for (int k0 = 0; k0 < Dd; k0 += 8) {
        float4 av = *(const float4*)(Z + (size_t)(row0 + am) * Dd + k0 + ak);
        float4 bv = *(const float4*)(Zt + (size_t)(k0 + bk) * Bn + col0 + bn);
        As[ak + 0][am] = av.x;
        As[ak + 1][am] = av.y;
        As[ak + 2][am] = av.z;
        As[ak + 3][am] = av.w;
        *(float4*)(&Bs[bk][bn]) = bv;
        __syncthreads();
        #pragma unroll
        for (int kk = 0; kk < 8; kk++) {
            float a[8], b[8];
            #pragma unroll
            for (int i = 0; i < 8; i++) a[i] = As[kk][ty * 8 + i];
            #pragma unroll
            for (int j = 0; j < 8; j++) b[j] = Bs[kk][tx * 8 + j];
            #pragma unroll
            for (int i = 0; i < 8; i++)
                #pragma unroll
                for (int j = 0; j < 8; j++) acc[i][j] = fmaf(a[i], b[j], acc[i][j]);
        }
        __syncthreads();
    }

    #pragma unroll
    for (int i = 0; i < 8; i++) {
        float rp = 0.f;
        #pragma unroll
        for (int j = 0; j < 8; j++) rp += __expf(acc[i][j] * INV_T);
        red[ty * 8 + i][tx] = rp;
    }
    __syncthreads();
    if (tid < 128) {
        float s = 0.f;
        #pragma unroll
        for (int t = 0; t < 16; t++) s += red[tid][t];
        atomicAdd(&rowsum[row0 + tid], s);
    }
}

// ---------------- small kernels ----------------
__global__ void zero_k() {
    int i = blockIdx.x * 256 + threadIdx.x;
    if (i < Bn)     g_reflsum[i] = 0.f;
    if (i < S * Bn) g_btwsum[i]  = 0.f;
    if (i < Cc * Dd) g_cbsum[i]  = 0.f;
}

// score[row] = dot(tanhbuf[row], q_w2), row in [0, S*Bn)
__global__ void score_k(const float* __restrict__ w2) {
    int warp = threadIdx.x >> 5, lane = threadIdx.x & 31;
    int row = blockIdx.x * 8 + warp;
    const float* tr = g_tanhbuf + (size_t)row * Dd;
    float s = 0.f;
    #pragma unroll
    for (int q = 0; q < 4; q++) {
        int d = lane + q * 32;
        s += tr[d] * w2[d];
    }
    #pragma unroll
    for (int o = 16; o > 0; o >>= 1) s += __shfl_down_sync(0xffffffffu, s, o);
    if (lane == 0) g_score[row] = s;
}

// softmax over sources + fuse; init res = fused, qsum = 0
__global__ void fuse_k() {
    int b = blockIdx.x, d = threadIdx.x;
    float s0 = g_score[b], s1 = g_score[Bn + b], s2 = g_score[2 * Bn + b];
    float mx = fmaxf(s0, fmaxf(s1, s2));
    float e0 = __expf(s0 - mx), e1 = __expf(s1 - mx), e2 = __expf(s2 - mx);
    float inv = 1.f / (e0 + e1 + e2);
    float f = inv * (e0 * g_emb[(size_t)b * Dd + d]
                   + e1 * g_emb[((size_t)Bn + b) * Dd + d]
                   + e2 * g_emb[((size_t)2 * Bn + b) * Dd + d]);
    g_res[b * Dd + d] = f;
    g_qsum[b * Dd + d] = 0.f;
}

// per codebook-row: ||e||^2 and 1/max(||e||, eps)
__global__ void enorm_k(const float* __restrict__ cb) {
    int warp = threadIdx.x >> 5, lane = threadIdx.x & 31;
    int row = blockIdx.x * 8 + warp;           // 0 .. C*K-1
    const float* e = cb + (size_t)row * Dd;
    float ss = 0.f;
    #pragma unroll
    for (int q = 0; q < 4; q++) {
        float v = e[lane + q * 32];
        ss += v * v;
    }
    #pragma unroll
    for (int o = 16; o > 0; o >>= 1) ss += __shfl_down_sync(0xffffffffu, ss, o);
    if (lane == 0) {
        g_enorm2[row] = ss;
        g_einvn[row] = 1.f / fmaxf(sqrtf(ss), 1e-12f);
    }
}

// transpose codebooks: Et[c][d][k] = cb[c][k][d]
__global__ void et_k(const float* __restrict__ cb) {
    int idx = blockIdx.x * 256 + threadIdx.x;
    if (idx >= Cc * Kc * Dd) return;
    int c = idx / (Kc * Dd);
    int r = idx % (Kc * Dd);
    int k = r / Dd, d = r % Dd;
    g_Et[((size_t)c * Dd + d) * Kc + k] = cb[idx];
}

// cbsum[c][d] = sum_k cb[c][k][d] * invnorm
__global__ void cbsum_k(const float* __restrict__ cb) {
    int c = blockIdx.y, kc = blockIdx.x, d = threadIdx.x;
    float acc = 0.f;
    for (int k = kc * 128; k < kc * 128 + 128; k++)
        acc += cb[((size_t)c * Kc + k) * Dd + d] * g_einvn[c * Kc + k];
    atomicAdd(&g_cbsum[c * Dd + d], acc);
}

// argmin over codes + straight-through update (qsum += e, res -= e)
__global__ void vq_step_k(int c, const float* __restrict__ cb) {
    __shared__ float sval[128];
    __shared__ int   sidx[128];
    int b = blockIdx.x, t = threadIdx.x;
    const float* en   = g_enorm2 + c * Kc;
    const float* drow = g_dots + (size_t)b * Kc;
    float best = 3.4e38f; int bi = 0;
    #pragma unroll
    for (int q = 0; q < 4; q++) {
        int k = t + q * 128;
        float v = en[k] - 2.f * drow[k];
        if (v < best) { best = v; bi = k; }
    }
    sval[t] = best; sidx[t] = bi;
    __syncthreads();
    #pragma unroll
    for (int s = 64; s > 0; s >>= 1) {
        if (t < s) {
            float ov = sval[t + s]; int oi = sidx[t + s];
            if (ov < sval[t] || (ov == sval[t] && oi < sidx[t])) { sval[t] = ov; sidx[t] = oi; }
        }
        __syncthreads();
    }
    int code = sidx[0];
    float e = cb[((size_t)c * Kc + code) * Dd + t];
    g_qsum[b * Dd + t] += e;
    g_res[b * Dd + t]  -= e;
}

__global__ void normz1_k() {
    int b = blockIdx.x, d = threadIdx.x;
    float v = g_qsum[b * Dd + d];
    float ss = blockReduceSum128(v * v);
    float z = v * (1.f / fmaxf(sqrtf(ss), 1e-12f));
    g_z1[b * Dd + d] = z;
    g_z1t[(size_t)d * Bn + b] = z;
}

__global__ void normz2_k() {
    int b = blockIdx.x, s = blockIdx.y, d = threadIdx.x;
    float v = g_emb[((size_t)s * Bn + b) * Dd + d];
    float ss = blockReduceSum128(v * v);
    float z = v * (1.f / fmaxf(sqrtf(ss), 1e-12f));
    g_z2[((size_t)s * Bn + b) * Dd + d] = z;
    g_z2t[(size_t)s * Dd * Bn + (size_t)d * Bn + b] = z;
}

__global__ void diagpos_k() {
    int b = blockIdx.x, d = threadIdx.x;
    float z = g_z1[b * Dd + d];
    float p0 = blockReduceSum128(z * z);
    float q0 = blockReduceSum128(z * g_z2[(size_t)b * Dd + d]);
    float q1 = blockReduceSum128(z * g_z2[((size_t)Bn + b) * Dd + d]);
    float q2 = blockReduceSum128(z * g_z2[((size_t)2 * Bn + b) * Dd + d]);
    if (d == 0) {
        g_diag[b] = __expf(p0 * INV_T);
        g_pos[b]            = __expf(q0 * INV_T);
        g_pos[Bn + b]       = __expf(q1 * INV_T);
        g_pos[2 * Bn + b]   = __expf(q2 * INV_T);
    }
}

__global__ void final_k(float* __restrict__ out) {
    __shared__ float sr[256];
    int t = threadIdx.x;

    float p = 0.f;
    if (t < 128) {
        #pragma unroll
        for (int m = 0; m < Cc; m++) {
            float v = g_cbsum[m * Dd + t];
            p += v * v;
        }
    }
    sr[t] = p;
    __syncthreads();
    #pragma unroll
    for (int s = 128; s > 0; s >>= 1) {
        if (t < s) sr[t] += sr[t + s];
        __syncthreads();
    }
    float cbloss = sr[0] / (float)(Cc * Kc * Kc);
    __syncthreads();

    float a0 = 0.f, a1 = 0.f, a2 = 0.f;
    for (int b = t; b < Bn; b += 256) {
        float rs = g_reflsum[b] - g_diag[b];
        a0 += logf(rs + g_btwsum[b])           - logf(g_pos[b]);
        a1 += logf(rs + g_btwsum[Bn + b])      - logf(g_pos[Bn + b]);
        a2 += logf(rs + g_btwsum[2 * Bn + b])  - logf(g_pos[2 * Bn + b]);
    }
    float av[3] = {a0, a1, a2};
    #pragma unroll
    for (int s = 0; s < 3; s++) {
        sr[t] = av[s];
        __syncthreads();
        for (int q = 128; q > 0; q >>= 1) {
            if (t < q) sr[t] += sr[t + q];
            __syncthreads();
        }
        if (t == 0) out[2 + s] = sr[0] / (float)Bn;
        __syncthreads();
    }
    if (t == 0) { out[0] = cbloss; out[1] = 0.f; }
}

// ---------------- host launcher ----------------
extern "C" void kernel_launch(void* const* d_in, const int* in_sizes, int n_in,
                              void* d_out, int out_size)
{
    const float* x   = (const float*)d_in[0];
    const float* ew1 = (const float*)d_in[1];  const float* eb1 = (const float*)d_in[2];
    const float* ew2 = (const float*)d_in[3];  const float* eb2 = (const float*)d_in[4];
    const float* ew3 = (const float*)d_in[5];  const float* eb3 = (const float*)d_in[6];
    const float* ew4 = (const float*)d_in[7];  const float* eb4 = (const float*)d_in[8];
    const float* qw1 = (const float*)d_in[9];  const float* qb1 = (const float*)d_in[10];
    const float* qw2 = (const float*)d_in[11];
    const float* cb  = (const float*)d_in[12];
    float* out = (float*)d_out;

    float *p_h1, *p_h2, *p_h3, *p_emb, *p_tanh, *p_res, *p_dots, *p_Et;
    cudaGetSymbolAddress((void**)&p_h1,   g_h1);
    cudaGetSymbolAddress((void**)&p_h2,   g_h2);
    cudaGetSymbolAddress((void**)&p_h3,   g_h3);
    cudaGetSymbolAddress((void**)&p_emb,  g_emb);
    cudaGetSymbolAddress((void**)&p_tanh, g_tanhbuf);
    cudaGetSymbolAddress((void**)&p_res,  g_res);
    cudaGetSymbolAddress((void**)&p_dots, g_dots);
    cudaGetSymbolAddress((void**)&p_Et,   g_Et);

    zero_k<<<(S * Bn + 255) / 256, 256>>>();

    // per-source MLP encoder (batched over z = s)
    sgemm_k<1><<<dim3(H1d / 128, Bn / 128, S), 256>>>(x,    ew1, eb1, p_h1,  H1d, DIN, Bn * DIN, DIN * H1d, H1d, Bn * H1d);
    sgemm_k<1><<<dim3(H2d / 128, Bn / 128, S), 256>>>(p_h1, ew2, eb2, p_h2,  H2d, H1d, Bn * H1d, H1d * H2d, H2d, Bn * H2d);
    sgemm_k<1><<<dim3(H3d / 128, Bn / 128, S), 256>>>(p_h2, ew3, eb3, p_h3,  H3d, H2d, Bn * H2d, H2d * H3d, H3d, Bn * H3d);
    sgemm_k<2><<<dim3(Dd  / 128, Bn / 128, S), 256>>>(p_h3, ew4, eb4, p_emb, Dd,  H3d, Bn * H3d, H3d * Dd,  Dd,  Bn * Dd);

    // attention: tanh(emb @ q_w1 + b1), dot with q_w2, softmax over s, fuse
    sgemm_k<3><<<dim3(1, (S * Bn) / 128, 1), 256>>>(p_emb, qw1, qb1, p_tanh, Dd, Dd, 0, 0, 0, 0);
    score_k<<<(S * Bn) / 8, 256>>>(qw2);
    fuse_k<<<Bn, 128>>>();

    // codebook prep
    enorm_k<<<(Cc * Kc) / 8, 256>>>(cb);
    et_k<<<(Cc * Kc * Dd + 255) / 256, 256>>>(cb);
    cbsum_k<<<dim3(Kc / 128, Cc), 128>>>(cb);

    // residual VQ (sequential over codebooks)
    for (int c = 0; c < Cc; c++) {
        sgemm_k<0><<<dim3(Kc / 128, Bn / 128, 1), 256>>>(p_res, p_Et + (size_t)c * Dd * Kc,
                                                         nullptr, p_dots, Kc, Dd, 0, 0, 0, 0);
        vq_step_k<<<Bn, 128>>>(c, cb);
    }

    // normalize + contrastive row-sums
    normz1_k<<<Bn, 128>>>();
    normz2_k<<<dim3(Bn, S), 128>>>();
    diagpos_k<<<Bn, 128>>>();
    for (int w = 0; w < 4; w++)
        rowsum_exp_k<<<dim3(Bn / 128, Bn / 128), 256>>>(w);

    final_k<<<1, 256>>>(out);
}

// round 4
// speedup vs baseline: 1.5714x; 1.5714x over previous
#include <cuda_runtime.h>

#define S   3
#define Bn  4096
#define DIN 1024
#define H1d 512
#define H2d 384
#define H3d 256
#define Dd  128
#define Kc  512
#define Cc  3
#define INV_T 10.0f

// ---------------- scratch (device globals; no allocation allowed) ----------------
__device__ float g_h1[S*Bn*H1d];
__device__ float g_h2[S*Bn*H2d];
__device__ float g_h3[S*Bn*H3d];
__device__ float g_emb[S*Bn*Dd];
__device__ float g_tanhbuf[S*Bn*Dd];
__device__ float g_score[S*Bn];
__device__ float g_res[Bn*Dd];
__device__ float g_qsum[Bn*Dd];
__device__ float g_dots[Bn*Kc];
__device__ float g_Et[Cc*Dd*Kc];
__device__ float g_enorm2[Cc*Kc];
__device__ float g_einvn[Cc*Kc];
__device__ float g_z1[Bn*Dd];
__device__ float g_z1t[Dd*Bn];
__device__ float g_z2[S*Bn*Dd];
__device__ float g_z2t[S*Dd*Bn];
__device__ float g_reflsum[Bn];
__device__ float g_btwsum[S*Bn];
__device__ float g_diag[Bn];
__device__ float g_pos[S*Bn];
__device__ float g_cbsum[Cc*Dd];

// ---------------- helpers ----------------
__device__ __forceinline__ float blockReduceSum128(float v) {
    __shared__ float sr[128];
    sr[threadIdx.x] = v;
    __syncthreads();
    #pragma unroll
    for (int s = 64; s > 0; s >>= 1) {
        if (threadIdx.x < s) sr[threadIdx.x] += sr[threadIdx.x + s];
        __syncthreads();
    }
    float r = sr[0];
    __syncthreads();
    return r;
}

__device__ __forceinline__ void cpa16(void* sm, const void* gm) {
    unsigned a = (unsigned)__cvta_generic_to_shared(sm);
    asm volatile("cp.async.cg.shared.global [%0], [%1], 16;" :: "r"(a), "l"(gm));
}
__device__ __forceinline__ void cpa_commit() {
    asm volatile("cp.async.commit_group;");
}

// Split fp32 into (hi, lo) tf32 pair: x ~= hi + lo with ~22 mantissa bits kept.
__device__ __forceinline__ void split_tf32(float x, unsigned &hi, unsigned &lo) {
    asm("cvt.rna.tf32.f32 %0, %1;" : "=r"(hi) : "f"(x));
    float r = x - __uint_as_float(hi);
    asm("cvt.rna.tf32.f32 %0, %1;" : "=r"(lo) : "f"(r));
}

__device__ __forceinline__ void mma_tf32(float* c, const unsigned* a, const unsigned* b) {
    asm volatile("mma.sync.aligned.m16n8k8.row.col.f32.tf32.tf32.f32 "
        "{%0,%1,%2,%3}, {%4,%5,%6,%7}, {%8,%9}, {%0,%1,%2,%3};"
        : "+f"(c[0]), "+f"(c[1]), "+f"(c[2]), "+f"(c[3])
        : "r"(a[0]), "r"(a[1]), "r"(a[2]), "r"(a[3]), "r"(b[0]), "r"(b[1]));
}

// ================= 3xTF32 tensor-core GEMM, 128x128 tile, 256 threads =================
// EPI: 0 = none, 1 = bias+relu, 2 = bias, 3 = tanh(x+bias)
// Main loop macro shared by tgemm_k and rowsum_t_k (2-stage cp.async pipeline).
#define TGEMM_MAINLOOP(Aptr, Bptr, Kdim, Ndim)                                          \
    __shared__ float As[2][128][20];                                                    \
    __shared__ float Bs[2][16][136];                                                    \
    const int tid = threadIdx.x;                                                        \
    const int warp = tid >> 5, lane = tid & 31;                                         \
    const int wm = warp & 1, wn = warp >> 1;                                            \
    const int group = lane >> 2, tid4 = lane & 3;                                       \
    const int row0 = blockIdx.y * 128, col0 = blockIdx.x * 128;                         \
    const int aRow = tid >> 2, aCol = (tid & 3) * 4;                                    \
    const int bRow = tid >> 5, bCol = (tid & 31) * 4;                                   \
    float acc[4][4][4];                                                                 \
    _Pragma("unroll")                                                                   \
    for (int i = 0; i < 4; i++)                                                         \
        _Pragma("unroll")                                                               \
        for (int j = 0; j < 4; j++)                                                     \
            _Pragma("unroll")                                                           \
            for (int q = 0; q < 4; q++) acc[i][j][q] = 0.f;                             \
    {                                                                                   \
        cpa16(&As[0][aRow][aCol],    Aptr + (size_t)(row0+aRow)*Kdim + aCol);           \
        cpa16(&As[0][aRow+64][aCol], Aptr + (size_t)(row0+aRow+64)*Kdim + aCol);        \
        cpa16(&Bs[0][bRow][bCol],    Bptr + (size_t)(bRow)*Ndim + col0 + bCol);         \
        cpa16(&Bs[0][bRow+8][bCol],  Bptr + (size_t)(bRow+8)*Ndim + col0 + bCol);       \
        cpa_commit();                                                                   \
    }                                                                                   \
    const int nT = (Kdim) >> 4;                                                         \
    for (int t = 0; t < nT; t++) {                                                      \
        if (t + 1 < nT) {                                                               \
            int k0 = (t + 1) << 4;                                                      \
            int s2 = (t + 1) & 1;                                                       \
            cpa16(&As[s2][aRow][aCol],    Aptr + (size_t)(row0+aRow)*Kdim + k0 + aCol); \
            cpa16(&As[s2][aRow+64][aCol], Aptr + (size_t)(row0+aRow+64)*Kdim + k0 + aCol);\
            cpa16(&Bs[s2][bRow][bCol],    Bptr + (size_t)(k0+bRow)*Ndim + col0 + bCol); \
            cpa16(&Bs[s2][bRow+8][bCol],  Bptr + (size_t)(k0+bRow+8)*Ndim + col0 + bCol);\
            cpa_commit();                                                               \
            asm volatile("cp.async.wait_group 1;");                                     \
        } else {                                                                        \
            asm volatile("cp.async.wait_group 0;");                                     \
        }                                                                               \
        __syncthreads();                                                                \
        const int sb = t & 1;                                                           \
        _Pragma("unroll")                                                               \
        for (int ks = 0; ks < 2; ks++) {                                                \
            const int kb = ks * 8;                                                      \
            unsigned ahi[4][4], alo[4][4];                                              \
            _Pragma("unroll")                                                           \
            for (int i = 0; i < 4; i++) {                                               \
                int mr = wm*64 + i*16 + group;                                          \
                split_tf32(As[sb][mr  ][kb+tid4  ], ahi[i][0], alo[i][0]);               \
                split_tf32(As[sb][mr+8][kb+tid4  ], ahi[i][1], alo[i][1]);               \
                split_tf32(As[sb][mr  ][kb+tid4+4], ahi[i][2], alo[i][2]);               \
                split_tf32(As[sb][mr+8][kb+tid4+4], ahi[i][3], alo[i][3]);               \
            }                                                                           \
            _Pragma("unroll")                                                           \
            for (int j = 0; j < 4; j++) {                                               \
                int nc = wn*32 + j*8 + group;                                           \
                unsigned bhi[2], blo[2];                                                \
                split_tf32(Bs[sb][kb+tid4  ][nc], bhi[0], blo[0]);                       \
                split_tf32(Bs[sb][kb+tid4+4][nc], bhi[1], blo[1]);                       \
                _Pragma("unroll")                                                       \
                for (int i = 0; i < 4; i++) {                                           \
                    mma_tf32(acc[i][j], ahi[i], bhi);                                   \
                    mma_tf32(acc[i][j], alo[i], bhi);                                   \
                    mma_tf32(acc[i][j], ahi[i], blo);                                   \
                }                                                                       \
            }                                                                           \
        }                                                                               \
        __syncthreads();                                                                \
    }

template<int EPI>
__global__ void __launch_bounds__(256)
tgemm_k(const float* __restrict__ A, const float* __restrict__ Bm,
        const float* __restrict__ bias, float* __restrict__ C,
        int N, int K, int sA, int sB, int sBias, int sC)
{
    A  += (size_t)blockIdx.z * sA;
    Bm += (size_t)blockIdx.z * sB;
    C  += (size_t)blockIdx.z * sC;
    if (EPI != 0) bias += (size_t)blockIdx.z * sBias;

    TGEMM_MAINLOOP(A, Bm, K, N)

    #pragma unroll
    for (int i = 0; i < 4; i++) {
        int row = row0 + wm*64 + i*16 + group;
        #pragma unroll
        for (int j = 0; j < 4; j++) {
            int col = col0 + wn*32 + j*8 + 2*tid4;
            float v0 = acc[i][j][0], v1 = acc[i][j][1];
            float v2 = acc[i][j][2], v3 = acc[i][j][3];
            if (EPI != 0) {
                float b0v = bias[col], b1v = bias[col+1];
                v0 += b0v; v1 += b1v; v2 += b0v; v3 += b1v;
                if (EPI == 1) {
                    v0 = fmaxf(v0, 0.f); v1 = fmaxf(v1, 0.f);
                    v2 = fmaxf(v2, 0.f); v3 = fmaxf(v3, 0.f);
                } else if (EPI == 3) {
                    v0 = tanhf(v0); v1 = tanhf(v1);
                    v2 = tanhf(v2); v3 = tanhf(v3);
                }
            }
            *(float2*)(C + (size_t)row * N + col)       = make_float2(v0, v1);
            *(float2*)(C + (size_t)(row + 8) * N + col) = make_float2(v2, v3);
        }
    }
}

// Contrastive: Z1 @ Zt, epilogue = row-sum of exp(v*INV_T). z=0: refl; z=1..3: between[s].
__global__ void __launch_bounds__(256)
rowsum_t_k()
{
    const int which = blockIdx.z;
    const float* __restrict__ A  = g_z1;
    const float* __restrict__ Bm = (which == 0) ? g_z1t
                                  : g_z2t + (size_t)(which - 1) * Dd * Bn;
    float* __restrict__ rowsum   = (which == 0) ? g_reflsum
                                  : g_btwsum + (size_t)(which - 1) * Bn;

    TGEMM_MAINLOOP(A, Bm, Dd, Bn)

    #pragma unroll
    for (int i = 0; i < 4; i++) {
        float sa = 0.f, sb2 = 0.f;
        #pragma unroll
        for (int j = 0; j < 4; j++) {
            sa  += __expf(acc[i][j][0] * INV_T) + __expf(acc[i][j][1] * INV_T);
            sb2 += __expf(acc[i][j][2] * INV_T) + __expf(acc[i][j][3] * INV_T);
        }
        // reduce across the 4 lanes of the quad (tid4 = 0..3)
        #pragma unroll
        for (int off = 1; off < 4; off <<= 1) {
            sa  += __shfl_xor_sync(0xffffffffu, sa,  off);
            sb2 += __shfl_xor_sync(0xffffffffu, sb2, off);
        }
        if (tid4 == 0) {
            int rowA = row0 + wm*64 + i*16 + group;
            atomicAdd(&rowsum[rowA],     sa);
            atomicAdd(&rowsum[rowA + 8], sb2);
        }
    }
}

// ---------------- small kernels (unchanged from passing version) ----------------
__global__ void zero_k() {
    int i = blockIdx.x * 256 + threadIdx.x;
    if (i < Bn)     g_reflsum[i] = 0.f;
    if (i < S * Bn) g_btwsum[i]  = 0.f;
    if (i < Cc * Dd) g_cbsum[i]  = 0.f;
}

__global__ void score_k(const float* __restrict__ w2) {
    int warp = threadIdx.x >> 5, lane = threadIdx.x & 31;
    int row = blockIdx.x * 8 + warp;
    const float* tr = g_tanhbuf + (size_t)row * Dd;
    float s = 0.f;
    #pragma unroll
    for (int q = 0; q < 4; q++) {
        int d = lane + q * 32;
        s += tr[d] * w2[d];
    }
    #pragma unroll
    for (int o = 16; o > 0; o >>= 1) s += __shfl_down_sync(0xffffffffu, s, o);
    if (lane == 0) g_score[row] = s;
}

__global__ void fuse_k() {
    int b = blockIdx.x, d = threadIdx.x;
    float s0 = g_score[b], s1 = g_score[Bn + b], s2 = g_score[2 * Bn + b];
    float mx = fmaxf(s0, fmaxf(s1, s2));
    float e0 = __expf(s0 - mx), e1 = __expf(s1 - mx), e2 = __expf(s2 - mx);
    float inv = 1.f / (e0 + e1 + e2);
    float f = inv * (e0 * g_emb[(size_t)b * Dd + d]
                   + e1 * g_emb[((size_t)Bn + b) * Dd + d]
                   + e2 * g_emb[((size_t)2 * Bn + b) * Dd + d]);
    g_res[b * Dd + d] = f;
    g_qsum[b * Dd + d] = 0.f;
}

__global__ void enorm_k(const float* __restrict__ cb) {
    int warp = threadIdx.x >> 5, lane = threadIdx.x & 31;
    int row = blockIdx.x * 8 + warp;
    const float* e = cb + (size_t)row * Dd;
    float ss = 0.f;
    #pragma unroll
    for (int q = 0; q < 4; q++) {
        float v = e[lane + q * 32];
        ss += v * v;
    }
    #pragma unroll
    for (int o = 16; o > 0; o >>= 1) ss += __shfl_down_sync(0xffffffffu, ss, o);
    if (lane == 0) {
        g_enorm2[row] = ss;
        g_einvn[row] = 1.f / fmaxf(sqrtf(ss), 1e-12f);
    }
}

__global__ void et_k(const float* __restrict__ cb) {
    int idx = blockIdx.x * 256 + threadIdx.x;
    if (idx >= Cc * Kc * Dd) return;
    int c = idx / (Kc * Dd);
    int r = idx % (Kc * Dd);
    int k = r / Dd, d = r % Dd;
    g_Et[((size_t)c * Dd + d) * Kc + k] = cb[idx];
}

__global__ void cbsum_k(const float* __restrict__ cb) {
    int c = blockIdx.y, kc = blockIdx.x, d = threadIdx.x;
    float acc = 0.f;
    for (int k = kc * 128; k < kc * 128 + 128; k++)
        acc += cb[((size_t)c * Kc + k) * Dd + d] * g_einvn[c * Kc + k];
    atomicAdd(&g_cbsum[c * Dd + d], acc);
}

__global__ void vq_step_k(int c, const float* __restrict__ cb) {
    __shared__ float sval[128];
    __shared__ int   sidx[128];
    int b = blockIdx.x, t = threadIdx.x;
    const float* en   = g_enorm2 + c * Kc;
    const float* drow = g_dots + (size_t)b * Kc;
    float best = 3.4e38f; int bi = 0;
    #pragma unroll
    for (int q = 0; q < 4; q++) {
        int k = t + q * 128;
        float v = en[k] - 2.f * drow[k];
        if (v < best) { best = v; bi = k; }
    }
    sval[t] = best; sidx[t] = bi;
    __syncthreads();
    #pragma unroll
    for (int s = 64; s > 0; s >>= 1) {
        if (t < s) {
            float ov = sval[t + s]; int oi = sidx[t + s];
            if (ov < sval[t] || (ov == sval[t] && oi < sidx[t])) { sval[t] = ov; sidx[t] = oi; }
        }
        __syncthreads();
    }
    int code = sidx[0];
    float e = cb[((size_t)c * Kc + code) * Dd + t];
    g_qsum[b * Dd + t] += e;
    g_res[b * Dd + t]  -= e;
}

__global__ void normz1_k() {
    int b = blockIdx.x, d = threadIdx.x;
    float v = g_qsum[b * Dd + d];
    float ss = blockReduceSum128(v * v);
    float z = v * (1.f / fmaxf(sqrtf(ss), 1e-12f));
    g_z1[b * Dd + d] = z;
    g_z1t[(size_t)d * Bn + b] = z;
}

__global__ void normz2_k() {
    int b = blockIdx.x, s = blockIdx.y, d = threadIdx.x;
    float v = g_emb[((size_t)s * Bn + b) * Dd + d];
    float ss = blockReduceSum128(v * v);
    float z = v * (1.f / fmaxf(sqrtf(ss), 1e-12f));
    g_z2[((size_t)s * Bn + b) * Dd + d] = z;
    g_z2t[(size_t)s * Dd * Bn + (size_t)d * Bn + b] = z;
}

__global__ void diagpos_k() {
    int b = blockIdx.x, d = threadIdx.x;
    float z = g_z1[b * Dd + d];
    float p0 = blockReduceSum128(z * z);
    float q0 = blockReduceSum128(z * g_z2[(size_t)b * Dd + d]);
    float q1 = blockReduceSum128(z * g_z2[((size_t)Bn + b) * Dd + d]);
    float q2 = blockReduceSum128(z * g_z2[((size_t)2 * Bn + b) * Dd + d]);
    if (d == 0) {
        g_diag[b] = __expf(p0 * INV_T);
        g_pos[b]            = __expf(q0 * INV_T);
        g_pos[Bn + b]       = __expf(q1 * INV_T);
        g_pos[2 * Bn + b]   = __expf(q2 * INV_T);
    }
}

__global__ void final_k(float* __restrict__ out) {
    __shared__ float sr[256];
    int t = threadIdx.x;

    float p = 0.f;
    if (t < 128) {
        #pragma unroll
        for (int m = 0; m < Cc; m++) {
            float v = g_cbsum[m * Dd + t];
            p += v * v;
        }
    }
    sr[t] = p;
    __syncthreads();
    #pragma unroll
    for (int s = 128; s > 0; s >>= 1) {
        if (t < s) sr[t] += sr[t + s];
        __syncthreads();
    }
    float cbloss = sr[0] / (float)(Cc * Kc * Kc);
    __syncthreads();

    float a0 = 0.f, a1 = 0.f, a2 = 0.f;
    for (int b = t; b < Bn; b += 256) {
        float rs = g_reflsum[b] - g_diag[b];
        a0 += logf(rs + g_btwsum[b])           - logf(g_pos[b]);
        a1 += logf(rs + g_btwsum[Bn + b])      - logf(g_pos[Bn + b]);
        a2 += logf(rs + g_btwsum[2 * Bn + b])  - logf(g_pos[2 * Bn + b]);
    }
    float av[3] = {a0, a1, a2};
    #pragma unroll
    for (int s = 0; s < 3; s++) {
        sr[t] = av[s];
        __syncthreads();
        for (int q = 128; q > 0; q >>= 1) {
            if (t < q) sr[t] += sr[t + q];
            __syncthreads();
        }
        if (t == 0) out[2 + s] = sr[0] / (float)Bn;
        __syncthreads();
    }
    if (t == 0) { out[0] = cbloss; out[1] = 0.f; }
}

// ---------------- host launcher ----------------
extern "C" void kernel_launch(void* const* d_in, const int* in_sizes, int n_in,
                              void* d_out, int out_size)
{
    const float* x   = (const float*)d_in[0];
    const float* ew1 = (const float*)d_in[1];  const float* eb1 = (const float*)d_in[2];
    const float* ew2 = (const float*)d_in[3];  const float* eb2 = (const float*)d_in[4];
    const float* ew3 = (const float*)d_in[5];  const float* eb3 = (const float*)d_in[6];
    const float* ew4 = (const float*)d_in[7];  const float* eb4 = (const float*)d_in[8];
    const float* qw1 = (const float*)d_in[9];  const float* qb1 = (const float*)d_in[10];
    const float* qw2 = (const float*)d_in[11];
    const float* cb  = (const float*)d_in[12];
    float* out = (float*)d_out;

    float *p_h1, *p_h2, *p_h3, *p_emb, *p_tanh, *p_res, *p_dots, *p_Et;
    cudaGetSymbolAddress((void**)&p_h1,   g_h1);
    cudaGetSymbolAddress((void**)&p_h2,   g_h2);
    cudaGetSymbolAddress((void**)&p_h3,   g_h3);
    cudaGetSymbolAddress((void**)&p_emb,  g_emb);
    cudaGetSymbolAddress((void**)&p_tanh, g_tanhbuf);
    cudaGetSymbolAddress((void**)&p_res,  g_res);
    cudaGetSymbolAddress((void**)&p_dots, g_dots);
    cudaGetSymbolAddress((void**)&p_Et,   g_Et);

    zero_k<<<(S * Bn + 255) / 256, 256>>>();

    // per-source MLP encoder (batched over z = s), 3xTF32 tensor cores
    tgemm_k<1><<<dim3(H1d / 128, Bn / 128, S), 256>>>(x,    ew1, eb1, p_h1,  H1d, DIN, Bn * DIN, DIN * H1d, H1d, Bn * H1d);
    tgemm_k<1><<<dim3(H2d / 128, Bn / 128, S), 256>>>(p_h1, ew2, eb2, p_h2,  H2d, H1d, Bn * H1d, H1d * H2d, H2d, Bn * H2d);
    tgemm_k<1><<<dim3(H3d / 128, Bn / 128, S), 256>>>(p_h2, ew3, eb3, p_h3,  H3d, H2d, Bn * H2d, H2d * H3d, H3d, Bn * H3d);
    tgemm_k<2><<<dim3(Dd  / 128, Bn / 128, S), 256>>>(p_h3, ew4, eb4, p_emb, Dd,  H3d, Bn * H3d, H3d * Dd,  Dd,  Bn * Dd);

    // attention: tanh(emb @ q_w1 + b1), dot with q_w2, softmax over s, fuse
    tgemm_k<3><<<dim3(1, (S * Bn) / 128, 1), 256>>>(p_emb, qw1, qb1, p_tanh, Dd, Dd, 0, 0, 0, 0);
    score_k<<<(S * Bn) / 8, 256>>>(qw2);
    fuse_k<<<Bn, 128>>>();

    // codebook prep
    enorm_k<<<(Cc * Kc) / 8, 256>>>(cb);
    et_k<<<(Cc * Kc * Dd + 255) / 256, 256>>>(cb);
    cbsum_k<<<dim3(Kc / 128, Cc), 128>>>(cb);

    // residual VQ (sequential over codebooks)
    for (int c = 0; c < Cc; c++) {
        tgemm_k<0><<<dim3(Kc / 128, Bn / 128, 1), 256>>>(p_res, p_Et + (size_t)c * Dd * Kc,
                                                         nullptr, p_dots, Kc, Dd, 0, 0, 0, 0);
        vq_step_k<<<Bn, 128>>>(c, cb);
    }

    // normalize + contrastive row-sums (all 4 Gram products in one launch)
    normz1_k<<<Bn, 128>>>();
    normz2_k<<<dim3(Bn, S), 128>>>();
    diagpos_k<<<Bn, 128>>>();
    rowsum_t_k<<<dim3(Bn / 128, Bn / 128, 4), 256>>>();

    final_k<<<1, 256>>>(out);
}

// round 5
// speedup vs baseline: 1.7619x; 1.1212x over previous
#include <cuda_runtime.h>

#define S   3
#define Bn  4096
#define DIN 1024
#define H1d 512
#define H2d 384
#define H3d 256
#define Dd  128
#define Kc  512
#define Cc  3
#define INV_T 10.0f
#define EXP10 22026.465794806718f   // exp(10) = refl-gram diagonal (z1 unit norm)

// ---------------- scratch (device globals; no allocation allowed) ----------------
__device__ float g_h1[S*Bn*H1d];
__device__ float g_h2[S*Bn*H2d];
__device__ float g_h3[S*Bn*H3d];
__device__ float g_emb[S*Bn*Dd];
__device__ float g_tanhbuf[S*Bn*Dd];
__device__ float g_res[Bn*Dd];
__device__ float g_qsum[Bn*Dd];
__device__ float g_dots[Bn*Kc];
__device__ float g_Et[Cc*Dd*Kc];
__device__ float g_enorm2[Cc*Kc];
__device__ float g_einvn[Cc*Kc];
__device__ float g_z1[Bn*Dd];
__device__ float g_z1t[Dd*Bn];
__device__ float g_z2[S*Bn*Dd];
__device__ float g_z2t[S*Dd*Bn];
__device__ float g_reflsum[Bn];
__device__ float g_btwsum[S*Bn];
__device__ float g_pos[S*Bn];
__device__ float g_cbsum[Cc*Dd];

// ---------------- helpers ----------------
__device__ __forceinline__ float blockReduceSum128(float v) {
    __shared__ float sr[128];
    sr[threadIdx.x] = v;
    __syncthreads();
    #pragma unroll
    for (int s = 64; s > 0; s >>= 1) {
        if (threadIdx.x < s) sr[threadIdx.x] += sr[threadIdx.x + s];
        __syncthreads();
    }
    float r = sr[0];
    __syncthreads();
    return r;
}

__device__ __forceinline__ void cpa16(void* sm, const void* gm) {
    unsigned a = (unsigned)__cvta_generic_to_shared(sm);
    asm volatile("cp.async.cg.shared.global [%0], [%1], 16;" :: "r"(a), "l"(gm));
}
__device__ __forceinline__ void cpa_commit() {
    asm volatile("cp.async.commit_group;");
}

// Fast tf32 split: NO cvt instructions.
// hi = x with low 13 mantissa bits cleared (exact RZ tf32) -> 1 LOP3
// lo = x - hi (exact fp32, <=13-bit significand)           -> 1 FADD
// mma.tf32 HW reads the top 19 bits of each operand; lo's extra 3 bits
// truncate at ~2^-20 relative -- negligible vs 1e-3 tolerance.
__device__ __forceinline__ void split_tf32(float x, unsigned &hi, unsigned &lo) {
    hi = __float_as_uint(x) & 0xffffe000u;
    lo = __float_as_uint(x - __uint_as_float(hi));
}

__device__ __forceinline__ void mma_tf32(float* c, const unsigned* a, const unsigned* b) {
    asm volatile("mma.sync.aligned.m16n8k8.row.col.f32.tf32.tf32.f32 "
        "{%0,%1,%2,%3}, {%4,%5,%6,%7}, {%8,%9}, {%0,%1,%2,%3};"
        : "+f"(c[0]), "+f"(c[1]), "+f"(c[2]), "+f"(c[3])
        : "r"(a[0]), "r"(a[1]), "r"(a[2]), "r"(a[3]), "r"(b[0]), "r"(b[1]));
}

// ================= 3xTF32 tensor-core GEMM, 128x128 tile, 256 threads =================
#define TGEMM_MAINLOOP(Aptr, Bptr, Kdim, Ndim)                                          \
    __shared__ float As[2][128][20];                                                    \
    __shared__ float Bs[2][16][136];                                                    \
    const int tid = threadIdx.x;                                                        \
    const int warp = tid >> 5, lane = tid & 31;                                         \
    const int wm = warp & 1, wn = warp >> 1;                                            \
    const int group = lane >> 2, tid4 = lane & 3;                                       \
    const int row0 = blockIdx.y * 128, col0 = blockIdx.x * 128;                         \
    const int aRow = tid >> 2, aCol = (tid & 3) * 4;                                    \
    const int bRow = tid >> 5, bCol = (tid & 31) * 4;                                   \
    float acc[4][4][4];                                                                 \
    _Pragma("unroll")                                                                   \
    for (int i = 0; i < 4; i++)                                                         \
        _Pragma("unroll")                                                               \
        for (int j = 0; j < 4; j++)                                                     \
            _Pragma("unroll")                                                           \
            for (int q = 0; q < 4; q++) acc[i][j][q] = 0.f;                             \
    {                                                                                   \
        cpa16(&As[0][aRow][aCol],    Aptr + (size_t)(row0+aRow)*Kdim + aCol);           \
        cpa16(&As[0][aRow+64][aCol], Aptr + (size_t)(row0+aRow+64)*Kdim + aCol);        \
        cpa16(&Bs[0][bRow][bCol],    Bptr + (size_t)(bRow)*Ndim + col0 + bCol);         \
        cpa16(&Bs[0][bRow+8][bCol],  Bptr + (size_t)(bRow+8)*Ndim + col0 + bCol);       \
        cpa_commit();                                                                   \
    }                                                                                   \
    const int nT = (Kdim) >> 4;                                                         \
    for (int t = 0; t < nT; t++) {                                                      \
        if (t + 1 < nT) {                                                               \
            int k0 = (t + 1) << 4;                                                      \
            int s2 = (t + 1) & 1;                                                       \
            cpa16(&As[s2][aRow][aCol],    Aptr + (size_t)(row0+aRow)*Kdim + k0 + aCol); \
            cpa16(&As[s2][aRow+64][aCol], Aptr + (size_t)(row0+aRow+64)*Kdim + k0 + aCol);\
            cpa16(&Bs[s2][bRow][bCol],    Bptr + (size_t)(k0+bRow)*Ndim + col0 + bCol); \
            cpa16(&Bs[s2][bRow+8][bCol],  Bptr + (size_t)(k0+bRow+8)*Ndim + col0 + bCol);\
            cpa_commit();                                                               \
            asm volatile("cp.async.wait_group 1;");                                     \
        } else {                                                                        \
            asm volatile("cp.async.wait_group 0;");                                     \
        }                                                                               \
        __syncthreads();                                                                \
        const int sb = t & 1;                                                           \
        _Pragma("unroll")                                                               \
        for (int ks = 0; ks < 2; ks++) {                                                \
            const int kb = ks * 8;                                                      \
            unsigned ahi[4][4], alo[4][4];                                              \
            _Pragma("unroll")                                                           \
            for (int i = 0; i < 4; i++) {                                               \
                int mr = wm*64 + i*16 + group;                                          \
                split_tf32(As[sb][mr  ][kb+tid4  ], ahi[i][0], alo[i][0]);               \
                split_tf32(As[sb][mr+8][kb+tid4  ], ahi[i][1], alo[i][1]);               \
                split_tf32(As[sb][mr  ][kb+tid4+4], ahi[i][2], alo[i][2]);               \
                split_tf32(As[sb][mr+8][kb+tid4+4], ahi[i][3], alo[i][3]);               \
            }                                                                           \
            unsigned bhi[4][2], blo[4][2];                                              \
            _Pragma("unroll")                                                           \
            for (int j = 0; j < 4; j++) {                                               \
                int nc = wn*32 + j*8 + group;                                           \
                split_tf32(Bs[sb][kb+tid4  ][nc], bhi[j][0], blo[j][0]);                 \
                split_tf32(Bs[sb][kb+tid4+4][nc], bhi[j][1], blo[j][1]);                 \
            }                                                                           \
            _Pragma("unroll")                                                           \
            for (int j = 0; j < 4; j++)                                                 \
                _Pragma("unroll")                                                       \
                for (int i = 0; i < 4; i++) {                                           \
                    mma_tf32(acc[i][j], ahi[i], bhi[j]);                                \
                    mma_tf32(acc[i][j], alo[i], bhi[j]);                                \
                    mma_tf32(acc[i][j], ahi[i], blo[j]);                                \
                }                                                                       \
        }                                                                               \
        __syncthreads();                                                                \
    }

// EPI: 0 = none, 1 = bias+relu, 2 = bias, 3 = tanh(x+bias)
template<int EPI>
__global__ void __launch_bounds__(256)
tgemm_k(const float* __restrict__ A, const float* __restrict__ Bm,
        const float* __restrict__ bias, float* __restrict__ C,
        int N, int K, int sA, int sB, int sBias, int sC)
{
    A  += (size_t)blockIdx.z * sA;
    Bm += (size_t)blockIdx.z * sB;
    C  += (size_t)blockIdx.z * sC;
    if (EPI != 0) bias += (size_t)blockIdx.z * sBias;

    TGEMM_MAINLOOP(A, Bm, K, N)

    #pragma unroll
    for (int i = 0; i < 4; i++) {
        int row = row0 + wm*64 + i*16 + group;
        #pragma unroll
        for (int j = 0; j < 4; j++) {
            int col = col0 + wn*32 + j*8 + 2*tid4;
            float v0 = acc[i][j][0], v1 = acc[i][j][1];
            float v2 = acc[i][j][2], v3 = acc[i][j][3];
            if (EPI != 0) {
                float b0v = bias[col], b1v = bias[col+1];
                v0 += b0v; v1 += b1v; v2 += b0v; v3 += b1v;
                if (EPI == 1) {
                    v0 = fmaxf(v0, 0.f); v1 = fmaxf(v1, 0.f);
                    v2 = fmaxf(v2, 0.f); v3 = fmaxf(v3, 0.f);
                } else if (EPI == 3) {
                    v0 = tanhf(v0); v1 = tanhf(v1);
                    v2 = tanhf(v2); v3 = tanhf(v3);
                }
            }
            *(float2*)(C + (size_t)row * N + col)       = make_float2(v0, v1);
            *(float2*)(C + (size_t)(row + 8) * N + col) = make_float2(v2, v3);
        }
    }
}

// Contrastive: Z1 @ Zt, epilogue = row-sum of exp(v*INV_T). z=0: refl; z=1..3: between[s].
__global__ void __launch_bounds__(256)
rowsum_t_k()
{
    const int which = blockIdx.z;
    const float* __restrict__ A  = g_z1;
    const float* __restrict__ Bm = (which == 0) ? g_z1t
                                  : g_z2t + (size_t)(which - 1) * Dd * Bn;
    float* __restrict__ rowsum   = (which == 0) ? g_reflsum
                                  : g_btwsum + (size_t)(which - 1) * Bn;

    TGEMM_MAINLOOP(A, Bm, Dd, Bn)

    #pragma unroll
    for (int i = 0; i < 4; i++) {
        float sa = 0.f, sb2 = 0.f;
        #pragma unroll
        for (int j = 0; j < 4; j++) {
            sa  += __expf(acc[i][j][0] * INV_T) + __expf(acc[i][j][1] * INV_T);
            sb2 += __expf(acc[i][j][2] * INV_T) + __expf(acc[i][j][3] * INV_T);
        }
        #pragma unroll
        for (int off = 1; off < 4; off <<= 1) {
            sa  += __shfl_xor_sync(0xffffffffu, sa,  off);
            sb2 += __shfl_xor_sync(0xffffffffu, sb2, off);
        }
        if (tid4 == 0) {
            int rowA = row0 + wm*64 + i*16 + group;
            atomicAdd(&rowsum[rowA],     sa);
            atomicAdd(&rowsum[rowA + 8], sb2);
        }
    }
}

// ---------------- small kernels ----------------
__global__ void zero_k() {
    int i = blockIdx.x * 256 + threadIdx.x;
    if (i < Bn)     g_reflsum[i] = 0.f;
    if (i < S * Bn) g_btwsum[i]  = 0.f;
    if (i < Cc * Dd) g_cbsum[i]  = 0.f;
}

// merged: per-source score dot + softmax over sources + fuse; res=fused, qsum=0
__global__ void fuse_score_k(const float* __restrict__ w2) {
    __shared__ float sc[3];
    int b = blockIdx.x, t = threadIdx.x;
    int w = t >> 5, lane = t & 31;
    if (w < 3) {
        const float* tr = g_tanhbuf + ((size_t)w * Bn + b) * Dd;
        float s = 0.f;
        #pragma unroll
        for (int q = 0; q < 4; q++) {
            int d = lane + q * 32;
            s += tr[d] * w2[d];
        }
        #pragma unroll
        for (int o = 16; o > 0; o >>= 1) s += __shfl_down_sync(0xffffffffu, s, o);
        if (lane == 0) sc[w] = s;
    }
    __syncthreads();
    float s0 = sc[0], s1 = sc[1], s2 = sc[2];
    float mx = fmaxf(s0, fmaxf(s1, s2));
    float e0 = __expf(s0 - mx), e1 = __expf(s1 - mx), e2 = __expf(s2 - mx);
    float inv = 1.f / (e0 + e1 + e2);
    int d = t;   // 128 threads = D
    float f = inv * (e0 * g_emb[(size_t)b * Dd + d]
                   + e1 * g_emb[((size_t)Bn + b) * Dd + d]
                   + e2 * g_emb[((size_t)2 * Bn + b) * Dd + d]);
    g_res[b * Dd + d] = f;
    g_qsum[b * Dd + d] = 0.f;
}

__global__ void enorm_k(const float* __restrict__ cb) {
    int warp = threadIdx.x >> 5, lane = threadIdx.x & 31;
    int row = blockIdx.x * 8 + warp;
    const float* e = cb + (size_t)row * Dd;
    float ss = 0.f;
    #pragma unroll
    for (int q = 0; q < 4; q++) {
        float v = e[lane + q * 32];
        ss += v * v;
    }
    #pragma unroll
    for (int o = 16; o > 0; o >>= 1) ss += __shfl_down_sync(0xffffffffu, ss, o);
    if (lane == 0) {
        g_enorm2[row] = ss;
        g_einvn[row] = 1.f / fmaxf(sqrtf(ss), 1e-12f);
    }
}

__global__ void et_k(const float* __restrict__ cb) {
    int idx = blockIdx.x * 256 + threadIdx.x;
    if (idx >= Cc * Kc * Dd) return;
    int c = idx / (Kc * Dd);
    int r = idx % (Kc * Dd);
    int k = r / Dd, d = r % Dd;
    g_Et[((size_t)c * Dd + d) * Kc + k] = cb[idx];
}

__global__ void cbsum_k(const float* __restrict__ cb) {
    int c = blockIdx.y, kc = blockIdx.x, d = threadIdx.x;
    float acc = 0.f;
    for (int k = kc * 128; k < kc * 128 + 128; k++)
        acc += cb[((size_t)c * Kc + k) * Dd + d] * g_einvn[c * Kc + k];
    atomicAdd(&g_cbsum[c * Dd + d], acc);
}

__global__ void vq_step_k(int c, const float* __restrict__ cb) {
    __shared__ float sval[128];
    __shared__ int   sidx[128];
    int b = blockIdx.x, t = threadIdx.x;
    const float* en   = g_enorm2 + c * Kc;
    const float* drow = g_dots + (size_t)b * Kc;
    float best = 3.4e38f; int bi = 0;
    #pragma unroll
    for (int q = 0; q < 4; q++) {
        int k = t + q * 128;
        float v = en[k] - 2.f * drow[k];
        if (v < best) { best = v; bi = k; }
    }
    sval[t] = best; sidx[t] = bi;
    __syncthreads();
    #pragma unroll
    for (int s = 64; s > 0; s >>= 1) {
        if (t < s) {
            float ov = sval[t + s]; int oi = sidx[t + s];
            if (ov < sval[t] || (ov == sval[t] && oi < sidx[t])) { sval[t] = ov; sidx[t] = oi; }
        }
        __syncthreads();
    }
    int code = sidx[0];
    float e = cb[((size_t)c * Kc + code) * Dd + t];
    g_qsum[b * Dd + t] += e;
    g_res[b * Dd + t]  -= e;
}

__global__ void normz1_k() {
    int b = blockIdx.x, d = threadIdx.x;
    float v = g_qsum[b * Dd + d];
    float ss = blockReduceSum128(v * v);
    float z = v * (1.f / fmaxf(sqrtf(ss), 1e-12f));
    g_z1[b * Dd + d] = z;
    g_z1t[(size_t)d * Bn + b] = z;
}

__global__ void normz2_k() {
    int b = blockIdx.x, s = blockIdx.y, d = threadIdx.x;
    float v = g_emb[((size_t)s * Bn + b) * Dd + d];
    float ss = blockReduceSum128(v * v);
    float z = v * (1.f / fmaxf(sqrtf(ss), 1e-12f));
    g_z2[((size_t)s * Bn + b) * Dd + d] = z;
    g_z2t[(size_t)s * Dd * Bn + (size_t)d * Bn + b] = z;
}

// positives only (refl diagonal is exp(10) by construction: z1 unit norm)
__global__ void pos_k() {
    int b = blockIdx.x, d = threadIdx.x;
    float z = g_z1[b * Dd + d];
    float q0 = blockReduceSum128(z * g_z2[(size_t)b * Dd + d]);
    float q1 = blockReduceSum128(z * g_z2[((size_t)Bn + b) * Dd + d]);
    float q2 = blockReduceSum128(z * g_z2[((size_t)2 * Bn + b) * Dd + d]);
    if (d == 0) {
        g_pos[b]          = __expf(q0 * INV_T);
        g_pos[Bn + b]     = __expf(q1 * INV_T);
        g_pos[2 * Bn + b] = __expf(q2 * INV_T);
    }
}

__global__ void final_k(float* __restrict__ out) {
    __shared__ float sr[256];
    int t = threadIdx.x;

    float p = 0.f;
    if (t < 128) {
        #pragma unroll
        for (int m = 0; m < Cc; m++) {
            float v = g_cbsum[m * Dd + t];
            p += v * v;
        }
    }
    sr[t] = p;
    __syncthreads();
    #pragma unroll
    for (int s = 128; s > 0; s >>= 1) {
        if (t < s) sr[t] += sr[t + s];
        __syncthreads();
    }
    float cbloss = sr[0] / (float)(Cc * Kc * Kc);
    __syncthreads();

    float a0 = 0.f, a1 = 0.f, a2 = 0.f;
    for (int b = t; b < Bn; b += 256) {
        float rs = g_reflsum[b] - EXP10;
        a0 += logf(rs + g_btwsum[b])           - logf(g_pos[b]);
        a1 += logf(rs + g_btwsum[Bn + b])      - logf(g_pos[Bn + b]);
        a2 += logf(rs + g_btwsum[2 * Bn + b])  - logf(g_pos[2 * Bn + b]);
    }
    float av[3] = {a0, a1, a2};
    #pragma unroll
    for (int s = 0; s < 3; s++) {
        sr[t] = av[s];
        __syncthreads();
        for (int q = 128; q > 0; q >>= 1) {
            if (t < q) sr[t] += sr[t + q];
            __syncthreads();
        }
        if (t == 0) out[2 + s] = sr[0] / (float)Bn;
        __syncthreads();
    }
    if (t == 0) { out[0] = cbloss; out[1] = 0.f; }
}

// ---------------- host launcher ----------------
extern "C" void kernel_launch(void* const* d_in, const int* in_sizes, int n_in,
                              void* d_out, int out_size)
{
    const float* x   = (const float*)d_in[0];
    const float* ew1 = (const float*)d_in[1];  const float* eb1 = (const float*)d_in[2];
    const float* ew2 = (const float*)d_in[3];  const float* eb2 = (const float*)d_in[4];
    const float* ew3 = (const float*)d_in[5];  const float* eb3 = (const float*)d_in[6];
    const float* ew4 = (const float*)d_in[7];  const float* eb4 = (const float*)d_in[8];
    const float* qw1 = (const float*)d_in[9];  const float* qb1 = (const float*)d_in[10];
    const float* qw2 = (const float*)d_in[11];
    const float* cb  = (const float*)d_in[12];
    float* out = (float*)d_out;

    float *p_h1, *p_h2, *p_h3, *p_emb, *p_tanh, *p_res, *p_dots, *p_Et;
    cudaGetSymbolAddress((void**)&p_h1,   g_h1);
    cudaGetSymbolAddress((void**)&p_h2,   g_h2);
    cudaGetSymbolAddress((void**)&p_h3,   g_h3);
    cudaGetSymbolAddress((void**)&p_emb,  g_emb);
    cudaGetSymbolAddress((void**)&p_tanh, g_tanhbuf);
    cudaGetSymbolAddress((void**)&p_res,  g_res);
    cudaGetSymbolAddress((void**)&p_dots, g_dots);
    cudaGetSymbolAddress((void**)&p_Et,   g_Et);

    zero_k<<<(S * Bn + 255) / 256, 256>>>();

    // per-source MLP encoder (batched over z = s), 3xTF32 tensor cores
    tgemm_k<1><<<dim3(H1d / 128, Bn / 128, S), 256>>>(x,    ew1, eb1, p_h1,  H1d, DIN, Bn * DIN, DIN * H1d, H1d, Bn * H1d);
    tgemm_k<1><<<dim3(H2d / 128, Bn / 128, S), 256>>>(p_h1, ew2, eb2, p_h2,  H2d, H1d, Bn * H1d, H1d * H2d, H2d, Bn * H2d);
    tgemm_k<1><<<dim3(H3d / 128, Bn / 128, S), 256>>>(p_h2, ew3, eb3, p_h3,  H3d, H2d, Bn * H2d, H2d * H3d, H3d, Bn * H3d);
    tgemm_k<2><<<dim3(Dd  / 128, Bn / 128, S), 256>>>(p_h3, ew4, eb4, p_emb, Dd,  H3d, Bn * H3d, H3d * Dd,  Dd,  Bn * Dd);

    // attention: tanh(emb @ q_w1 + b1), dot with q_w2, softmax over s, fuse
    tgemm_k<3><<<dim3(1, (S * Bn) / 128, 1), 256>>>(p_emb, qw1, qb1, p_tanh, Dd, Dd, 0, 0, 0, 0);
    fuse_score_k<<<Bn, 128>>>(qw2);

    // codebook prep
    enorm_k<<<(Cc * Kc) / 8, 256>>>(cb);
    et_k<<<(Cc * Kc * Dd + 255) / 256, 256>>>(cb);
    cbsum_k<<<dim3(Kc / 128, Cc), 128>>>(cb);

    // residual VQ (sequential over codebooks)
    for (int c = 0; c < Cc; c++) {
        tgemm_k<0><<<dim3(Kc / 128, Bn / 128, 1), 256>>>(p_res, p_Et + (size_t)c * Dd * Kc,
                                                         nullptr, p_dots, Kc, Dd, 0, 0, 0, 0);
        vq_step_k<<<Bn, 128>>>(c, cb);
    }

    // normalize + contrastive row-sums (all 4 Gram products in one launch)
    normz1_k<<<Bn, 128>>>();
    normz2_k<<<dim3(Bn, S), 128>>>();
    pos_k<<<Bn, 128>>>();
    rowsum_t_k<<<dim3(Bn / 128, Bn / 128, 4), 256>>>();

    final_k<<<1, 256>>>(out);
}

// round 6
// speedup vs baseline: 1.8513x; 1.0507x over previous
#include <cuda_runtime.h>

#define S   3
#define Bn  4096
#define DIN 1024
#define H1d 512
#define H2d 384
#define H3d 256
#define Dd  128
#define Kc  512
#define Cc  3
#define INV_T 10.0f
#define EXP10 22026.465794806718f   // exp(10) = refl-gram diagonal (z1 unit norm)

// ---------------- scratch (device globals; no allocation allowed) ----------------
__device__ float g_h1[S*Bn*H1d];
__device__ float g_h2[S*Bn*H2d];
__device__ float g_h3[S*Bn*H3d];
__device__ float g_emb[S*Bn*Dd];
__device__ float g_tanhbuf[S*Bn*Dd];
__device__ float g_res[Bn*Dd];
__device__ float g_qsum[Bn*Dd];
__device__ float g_dots[Bn*Kc];
__device__ float g_Et[Cc*Dd*Kc];
__device__ float g_enorm2[Cc*Kc];
__device__ float g_einvn[Cc*Kc];
__device__ float g_z1[Bn*Dd];
__device__ float g_z1t[Dd*Bn];
__device__ float g_z2[S*Bn*Dd];
__device__ float g_z2t[S*Dd*Bn];
__device__ float g_reflsum[Bn];
__device__ float g_btwsum[S*Bn];
__device__ float g_pos[S*Bn];
__device__ float g_cbsum[Cc*Dd];

// ---------------- helpers ----------------
__device__ __forceinline__ float blockReduceSum128(float v) {
    __shared__ float sr[128];
    sr[threadIdx.x] = v;
    __syncthreads();
    #pragma unroll
    for (int s = 64; s > 0; s >>= 1) {
        if (threadIdx.x < s) sr[threadIdx.x] += sr[threadIdx.x + s];
        __syncthreads();
    }
    float r = sr[0];
    __syncthreads();
    return r;
}

__device__ __forceinline__ void cpa16(void* sm, const void* gm) {
    unsigned a = (unsigned)__cvta_generic_to_shared(sm);
    asm volatile("cp.async.cg.shared.global [%0], [%1], 16;" :: "r"(a), "l"(gm));
}
__device__ __forceinline__ void cpa_commit() {
    asm volatile("cp.async.commit_group;");
}

// Fast tf32 split (no cvt): hi = x with low 13 mantissa bits cleared (1 LOP3),
// lo = x - hi (1 FADD). mma.tf32 HW reads top 19 bits of each operand.
__device__ __forceinline__ void split_tf32(float x, unsigned &hi, unsigned &lo) {
    hi = __float_as_uint(x) & 0xffffe000u;
    lo = __float_as_uint(x - __uint_as_float(hi));
}

__device__ __forceinline__ void mma_tf32(float* c, const unsigned* a, const unsigned* b) {
    asm volatile("mma.sync.aligned.m16n8k8.row.col.f32.tf32.tf32.f32 "
        "{%0,%1,%2,%3}, {%4,%5,%6,%7}, {%8,%9}, {%0,%1,%2,%3};"
        : "+f"(c[0]), "+f"(c[1]), "+f"(c[2]), "+f"(c[3])
        : "r"(a[0]), "r"(a[1]), "r"(a[2]), "r"(a[3]), "r"(b[0]), "r"(b[1]));
}

// ================= 3xTF32 tensor-core GEMM, 128x128 tile, 256 threads ================
// Register-lean inner loop: B-fragment splits hoisted per k-substep, A row-pairs
// streamed one at a time, so 2 CTAs fit per SM (launch_bounds(256,2) -> <=128 regs).
#define TGEMM_MAINLOOP(Aptr, Bptr, Kdim, Ndim)                                          \
    __shared__ float As[2][128][20];                                                    \
    __shared__ float Bs[2][16][136];                                                    \
    const int tid = threadIdx.x;                                                        \
    const int warp = tid >> 5, lane = tid & 31;                                         \
    const int wm = warp & 1, wn = warp >> 1;                                            \
    const int group = lane >> 2, tid4 = lane & 3;                                       \
    const int row0 = blockIdx.y * 128, col0 = blockIdx.x * 128;                         \
    const int aRow = tid >> 2, aCol = (tid & 3) * 4;                                    \
    const int bRow = tid >> 5, bCol = (tid & 31) * 4;                                   \
    float acc[4][4][4];                                                                 \
    _Pragma("unroll")                                                                   \
    for (int i = 0; i < 4; i++)                                                         \
        _Pragma("unroll")                                                               \
        for (int j = 0; j < 4; j++)                                                     \
            _Pragma("unroll")                                                           \
            for (int q = 0; q < 4; q++) acc[i][j][q] = 0.f;                             \
    {                                                                                   \
        cpa16(&As[0][aRow][aCol],    Aptr + (size_t)(row0+aRow)*Kdim + aCol);           \
        cpa16(&As[0][aRow+64][aCol], Aptr + (size_t)(row0+aRow+64)*Kdim + aCol);        \
        cpa16(&Bs[0][bRow][bCol],    Bptr + (size_t)(bRow)*Ndim + col0 + bCol);         \
        cpa16(&Bs[0][bRow+8][bCol],  Bptr + (size_t)(bRow+8)*Ndim + col0 + bCol);       \
        cpa_commit();                                                                   \
    }                                                                                   \
    const int nT = (Kdim) >> 4;                                                         \
    for (int t = 0; t < nT; t++) {                                                      \
        if (t + 1 < nT) {                                                               \
            int k0 = (t + 1) << 4;                                                      \
            int s2 = (t + 1) & 1;                                                       \
            cpa16(&As[s2][aRow][aCol],    Aptr + (size_t)(row0+aRow)*Kdim + k0 + aCol); \
            cpa16(&As[s2][aRow+64][aCol], Aptr + (size_t)(row0+aRow+64)*Kdim + k0 + aCol);\
            cpa16(&Bs[s2][bRow][bCol],    Bptr + (size_t)(k0+bRow)*Ndim + col0 + bCol); \
            cpa16(&Bs[s2][bRow+8][bCol],  Bptr + (size_t)(k0+bRow+8)*Ndim + col0 + bCol);\
            cpa_commit();                                                               \
            asm volatile("cp.async.wait_group 1;");                                     \
        } else {                                                                        \
            asm volatile("cp.async.wait_group 0;");                                     \
        }                                                                               \
        __syncthreads();                                                                \
        const int sb = t & 1;                                                           \
        _Pragma("unroll")                                                               \
        for (int ks = 0; ks < 2; ks++) {                                                \
            const int kb = ks * 8;                                                      \
            unsigned bhi[4][2], blo[4][2];                                              \
            _Pragma("unroll")                                                           \
            for (int j = 0; j < 4; j++) {                                               \
                int nc = wn*32 + j*8 + group;                                           \
                split_tf32(Bs[sb][kb+tid4  ][nc], bhi[j][0], blo[j][0]);                 \
                split_tf32(Bs[sb][kb+tid4+4][nc], bhi[j][1], blo[j][1]);                 \
            }                                                                           \
            _Pragma("unroll")                                                           \
            for (int i = 0; i < 4; i++) {                                               \
                int mr = wm*64 + i*16 + group;                                          \
                unsigned ahi[4], alo[4];                                                \
                split_tf32(As[sb][mr  ][kb+tid4  ], ahi[0], alo[0]);                     \
                split_tf32(As[sb][mr+8][kb+tid4  ], ahi[1], alo[1]);                     \
                split_tf32(As[sb][mr  ][kb+tid4+4], ahi[2], alo[2]);                     \
                split_tf32(As[sb][mr+8][kb+tid4+4], ahi[3], alo[3]);                     \
                _Pragma("unroll")                                                       \
                for (int j = 0; j < 4; j++) {                                           \
                    mma_tf32(acc[i][j], ahi, bhi[j]);                                   \
                    mma_tf32(acc[i][j], alo, bhi[j]);                                   \
                    mma_tf32(acc[i][j], ahi, blo[j]);                                   \
                }                                                                       \
            }                                                                           \
        }                                                                               \
        __syncthreads();                                                                \
    }

// EPI: 0 = none, 1 = bias+relu, 2 = bias, 3 = tanh(x+bias)
template<int EPI>
__global__ void __launch_bounds__(256, 2)
tgemm_k(const float* __restrict__ A, const float* __restrict__ Bm,
        const float* __restrict__ bias, float* __restrict__ C,
        int N, int K, int sA, int sB, int sBias, int sC)
{
    A  += (size_t)blockIdx.z * sA;
    Bm += (size_t)blockIdx.z * sB;
    C  += (size_t)blockIdx.z * sC;
    if (EPI != 0) bias += (size_t)blockIdx.z * sBias;

    TGEMM_MAINLOOP(A, Bm, K, N)

    #pragma unroll
    for (int i = 0; i < 4; i++) {
        int row = row0 + wm*64 + i*16 + group;
        #pragma unroll
        for (int j = 0; j < 4; j++) {
            int col = col0 + wn*32 + j*8 + 2*tid4;
            float v0 = acc[i][j][0], v1 = acc[i][j][1];
            float v2 = acc[i][j][2], v3 = acc[i][j][3];
            if (EPI != 0) {
                float b0v = bias[col], b1v = bias[col+1];
                v0 += b0v; v1 += b1v; v2 += b0v; v3 += b1v;
                if (EPI == 1) {
                    v0 = fmaxf(v0, 0.f); v1 = fmaxf(v1, 0.f);
                    v2 = fmaxf(v2, 0.f); v3 = fmaxf(v3, 0.f);
                } else if (EPI == 3) {
                    v0 = tanhf(v0); v1 = tanhf(v1);
                    v2 = tanhf(v2); v3 = tanhf(v3);
                }
            }
            *(float2*)(C + (size_t)row * N + col)       = make_float2(v0, v1);
            *(float2*)(C + (size_t)(row + 8) * N + col) = make_float2(v2, v3);
        }
    }
}

// Contrastive: Z1 @ Zt, epilogue = row-sum of exp(v*INV_T). z=0: refl; z=1..3: between[s].
__global__ void __launch_bounds__(256, 2)
rowsum_t_k()
{
    const int which = blockIdx.z;
    const float* __restrict__ A  = g_z1;
    const float* __restrict__ Bm = (which == 0) ? g_z1t
                                  : g_z2t + (size_t)(which - 1) * Dd * Bn;
    float* __restrict__ rowsum   = (which == 0) ? g_reflsum
                                  : g_btwsum + (size_t)(which - 1) * Bn;

    TGEMM_MAINLOOP(A, Bm, Dd, Bn)

    #pragma unroll
    for (int i = 0; i < 4; i++) {
        float sa = 0.f, sb2 = 0.f;
        #pragma unroll
        for (int j = 0; j < 4; j++) {
            sa  += __expf(acc[i][j][0] * INV_T) + __expf(acc[i][j][1] * INV_T);
            sb2 += __expf(acc[i][j][2] * INV_T) + __expf(acc[i][j][3] * INV_T);
        }
        #pragma unroll
        for (int off = 1; off < 4; off <<= 1) {
            sa  += __shfl_xor_sync(0xffffffffu, sa,  off);
            sb2 += __shfl_xor_sync(0xffffffffu, sb2, off);
        }
        if (tid4 == 0) {
            int rowA = row0 + wm*64 + i*16 + group;
            atomicAdd(&rowsum[rowA],     sa);
            atomicAdd(&rowsum[rowA + 8], sb2);
        }
    }
}

// ---------------- small kernels ----------------
__global__ void zero_k() {
    int i = blockIdx.x * 256 + threadIdx.x;
    if (i < Bn)     g_reflsum[i] = 0.f;
    if (i < S * Bn) g_btwsum[i]  = 0.f;
    if (i < Cc * Dd) g_cbsum[i]  = 0.f;
}

// merged: per-source score dot + softmax over sources + fuse; res=fused, qsum=0
__global__ void fuse_score_k(const float* __restrict__ w2) {
    __shared__ float sc[3];
    int b = blockIdx.x, t = threadIdx.x;
    int w = t >> 5, lane = t & 31;
    if (w < 3) {
        const float* tr = g_tanhbuf + ((size_t)w * Bn + b) * Dd;
        float s = 0.f;
        #pragma unroll
        for (int q = 0; q < 4; q++) {
            int d = lane + q * 32;
            s += tr[d] * w2[d];
        }
        #pragma unroll
        for (int o = 16; o > 0; o >>= 1) s += __shfl_down_sync(0xffffffffu, s, o);
        if (lane == 0) sc[w] = s;
    }
    __syncthreads();
    float s0 = sc[0], s1 = sc[1], s2 = sc[2];
    float mx = fmaxf(s0, fmaxf(s1, s2));
    float e0 = __expf(s0 - mx), e1 = __expf(s1 - mx), e2 = __expf(s2 - mx);
    float inv = 1.f / (e0 + e1 + e2);
    int d = t;
    float f = inv * (e0 * g_emb[(size_t)b * Dd + d]
                   + e1 * g_emb[((size_t)Bn + b) * Dd + d]
                   + e2 * g_emb[((size_t)2 * Bn + b) * Dd + d]);
    g_res[b * Dd + d] = f;
    g_qsum[b * Dd + d] = 0.f;
}

__global__ void enorm_k(const float* __restrict__ cb) {
    int warp = threadIdx.x >> 5, lane = threadIdx.x & 31;
    int row = blockIdx.x * 8 + warp;
    const float* e = cb + (size_t)row * Dd;
    float ss = 0.f;
    #pragma unroll
    for (int q = 0; q < 4; q++) {
        float v = e[lane + q * 32];
        ss += v * v;
    }
    #pragma unroll
    for (int o = 16; o > 0; o >>= 1) ss += __shfl_down_sync(0xffffffffu, ss, o);
    if (lane == 0) {
        g_enorm2[row] = ss;
        g_einvn[row] = 1.f / fmaxf(sqrtf(ss), 1e-12f);
    }
}

__global__ void et_k(const float* __restrict__ cb) {
    int idx = blockIdx.x * 256 + threadIdx.x;
    if (idx >= Cc * Kc * Dd) return;
    int c = idx / (Kc * Dd);
    int r = idx % (Kc * Dd);
    int k = r / Dd, d = r % Dd;
    g_Et[((size_t)c * Dd + d) * Kc + k] = cb[idx];
}

__global__ void cbsum_k(const float* __restrict__ cb) {
    int c = blockIdx.y, kc = blockIdx.x, d = threadIdx.x;
    float acc = 0.f;
    for (int k = kc * 128; k < kc * 128 + 128; k++)
        acc += cb[((size_t)c * Kc + k) * Dd + d] * g_einvn[c * Kc + k];
    atomicAdd(&g_cbsum[c * Dd + d], acc);
}

__global__ void vq_step_k(int c, const float* __restrict__ cb) {
    __shared__ float sval[128];
    __shared__ int   sidx[128];
    int b = blockIdx.x, t = threadIdx.x;
    const float* en   = g_enorm2 + c * Kc;
    const float* drow = g_dots + (size_t)b * Kc;
    float best = 3.4e38f; int bi = 0;
    #pragma unroll
    for (int q = 0; q < 4; q++) {
        int k = t + q * 128;
        float v = en[k] - 2.f * drow[k];
        if (v < best) { best = v; bi = k; }
    }
    sval[t] = best; sidx[t] = bi;
    __syncthreads();
    #pragma unroll
    for (int s = 64; s > 0; s >>= 1) {
        if (t < s) {
            float ov = sval[t + s]; int oi = sidx[t + s];
            if (ov < sval[t] || (ov == sval[t] && oi < sidx[t])) { sval[t] = ov; sidx[t] = oi; }
        }
        __syncthreads();
    }
    int code = sidx[0];
    float e = cb[((size_t)c * Kc + code) * Dd + t];
    g_qsum[b * Dd + t] += e;
    g_res[b * Dd + t]  -= e;
}

__global__ void normz1_k() {
    int b = blockIdx.x, d = threadIdx.x;
    float v = g_qsum[b * Dd + d];
    float ss = blockReduceSum128(v * v);
    float z = v * (1.f / fmaxf(sqrtf(ss), 1e-12f));
    g_z1[b * Dd + d] = z;
    g_z1t[(size_t)d * Bn + b] = z;
}

__global__ void normz2_k() {
    int b = blockIdx.x, s = blockIdx.y, d = threadIdx.x;
    float v = g_emb[((size_t)s * Bn + b) * Dd + d];
    float ss = blockReduceSum128(v * v);
    float z = v * (1.f / fmaxf(sqrtf(ss), 1e-12f));
    g_z2[((size_t)s * Bn + b) * Dd + d] = z;
    g_z2t[(size_t)s * Dd * Bn + (size_t)d * Bn + b] = z;
}

// positives only (refl diagonal is exp(10) by construction: z1 unit norm)
__global__ void pos_k() {
    int b = blockIdx.x, d = threadIdx.x;
    float z = g_z1[b * Dd + d];
    float q0 = blockReduceSum128(z * g_z2[(size_t)b * Dd + d]);
    float q1 = blockReduceSum128(z * g_z2[((size_t)Bn + b) * Dd + d]);
    float q2 = blockReduceSum128(z * g_z2[((size_t)2 * Bn + b) * Dd + d]);
    if (d == 0) {
        g_pos[b]          = __expf(q0 * INV_T);
        g_pos[Bn + b]     = __expf(q1 * INV_T);
        g_pos[2 * Bn + b] = __expf(q2 * INV_T);
    }
}

__global__ void final_k(float* __restrict__ out) {
    __shared__ float sr[256];
    int t = threadIdx.x;

    float p = 0.f;
    if (t < 128) {
        #pragma unroll
        for (int m = 0; m < Cc; m++) {
            float v = g_cbsum[m * Dd + t];
            p += v * v;
        }
    }
    sr[t] = p;
    __syncthreads();
    #pragma unroll
    for (int s = 128; s > 0; s >>= 1) {
        if (t < s) sr[t] += sr[t + s];
        __syncthreads();
    }
    float cbloss = sr[0] / (float)(Cc * Kc * Kc);
    __syncthreads();

    float a0 = 0.f, a1 = 0.f, a2 = 0.f;
    for (int b = t; b < Bn; b += 256) {
        float rs = g_reflsum[b] - EXP10;
        a0 += logf(rs + g_btwsum[b])           - logf(g_pos[b]);
        a1 += logf(rs + g_btwsum[Bn + b])      - logf(g_pos[Bn + b]);
        a2 += logf(rs + g_btwsum[2 * Bn + b])  - logf(g_pos[2 * Bn + b]);
    }
    float av[3] = {a0, a1, a2};
    #pragma unroll
    for (int s = 0; s < 3; s++) {
        sr[t] = av[s];
        __syncthreads();
        for (int q = 128; q > 0; q >>= 1) {
            if (t < q) sr[t] += sr[t + q];
            __syncthreads();
        }
        if (t == 0) out[2 + s] = sr[0] / (float)Bn;
        __syncthreads();
    }
    if (t == 0) { out[0] = cbloss; out[1] = 0.f; }
}

// ---------------- host launcher ----------------
extern "C" void kernel_launch(void* const* d_in, const int* in_sizes, int n_in,
                              void* d_out, int out_size)
{
    const float* x   = (const float*)d_in[0];
    const float* ew1 = (const float*)d_in[1];  const float* eb1 = (const float*)d_in[2];
    const float* ew2 = (const float*)d_in[3];  const float* eb2 = (const float*)d_in[4];
    const float* ew3 = (const float*)d_in[5];  const float* eb3 = (const float*)d_in[6];
    const float* ew4 = (const float*)d_in[7];  const float* eb4 = (const float*)d_in[8];
    const float* qw1 = (const float*)d_in[9];  const float* qb1 = (const float*)d_in[10];
    const float* qw2 = (const float*)d_in[11];
    const float* cb  = (const float*)d_in[12];
    float* out = (float*)d_out;

    float *p_h1, *p_h2, *p_h3, *p_emb, *p_tanh, *p_res, *p_dots, *p_Et;
    cudaGetSymbolAddress((void**)&p_h1,   g_h1);
    cudaGetSymbolAddress((void**)&p_h2,   g_h2);
    cudaGetSymbolAddress((void**)&p_h3,   g_h3);
    cudaGetSymbolAddress((void**)&p_emb,  g_emb);
    cudaGetSymbolAddress((void**)&p_tanh, g_tanhbuf);
    cudaGetSymbolAddress((void**)&p_res,  g_res);
    cudaGetSymbolAddress((void**)&p_dots, g_dots);
    cudaGetSymbolAddress((void**)&p_Et,   g_Et);

    zero_k<<<(S * Bn + 255) / 256, 256>>>();

    // per-source MLP encoder (batched over z = s), 3xTF32 tensor cores
    tgemm_k<1><<<dim3(H1d / 128, Bn / 128, S), 256>>>(x,    ew1, eb1, p_h1,  H1d, DIN, Bn * DIN, DIN * H1d, H1d, Bn * H1d);
    tgemm_k<1><<<dim3(H2d / 128, Bn / 128, S), 256>>>(p_h1, ew2, eb2, p_h2,  H2d, H1d, Bn * H1d, H1d * H2d, H2d, Bn * H2d);
    tgemm_k<1><<<dim3(H3d / 128, Bn / 128, S), 256>>>(p_h2, ew3, eb3, p_h3,  H3d, H2d, Bn * H2d, H2d * H3d, H3d, Bn * H3d);
    tgemm_k<2><<<dim3(Dd  / 128, Bn / 128, S), 256>>>(p_h3, ew4, eb4, p_emb, Dd,  H3d, Bn * H3d, H3d * Dd,  Dd,  Bn * Dd);

    // attention: tanh(emb @ q_w1 + b1), dot with q_w2, softmax over s, fuse
    tgemm_k<3><<<dim3(1, (S * Bn) / 128, 1), 256>>>(p_emb, qw1, qb1, p_tanh, Dd, Dd, 0, 0, 0, 0);
    fuse_score_k<<<Bn, 128>>>(qw2);

    // codebook prep
    enorm_k<<<(Cc * Kc) / 8, 256>>>(cb);
    et_k<<<(Cc * Kc * Dd + 255) / 256, 256>>>(cb);
    cbsum_k<<<dim3(Kc / 128, Cc), 128>>>(cb);

    // residual VQ (sequential over codebooks)
    for (int c = 0; c < Cc; c++) {
        tgemm_k<0><<<dim3(Kc / 128, Bn / 128, 1), 256>>>(p_res, p_Et + (size_t)c * Dd * Kc,
                                                         nullptr, p_dots, Kc, Dd, 0, 0, 0, 0);
        vq_step_k<<<Bn, 128>>>(c, cb);
    }

    // normalize + contrastive row-sums (all 4 Gram products in one launch)
    normz1_k<<<Bn, 128>>>();
    normz2_k<<<dim3(Bn, S), 128>>>();
    pos_k<<<Bn, 128>>>();
    rowsum_t_k<<<dim3(Bn / 128, Bn / 128, 4), 256>>>();

    final_k<<<1, 256>>>(out);
}